// round 3
// baseline (speedup 1.0000x reference)
#include <cuda_runtime.h>
#include <cstdint>

// ---------------------------------------------------------------------------
// YOLOv3 detector heads: three fused (1x1 conv GEMM -> decode) kernels.
//   per batch b:  P[b] = W (255 x K) * F[b] (K x HW) + bias
//   decode: sigmoid / exp / grid offsets / anchor scaling, scatter to
//   out[b, a*HW + n, attr]  (attr = channel % 85, a = channel / 85)
//
// GEMM: block computes M=256 (255 padded) x N=64 tile, K-chunks of 16 via
// shared memory. Inner product uses packed fma.rn.f32x2 -- two fp32 FMAs per
// issue slot, bit-identical to scalar fmaf. B operands are stored into smem
// pre-duplicated as {v,v} pairs so they load via broadcast LDS.128 with no
// per-step MOVs. A fragments are two float4s at m = tm*4 and m = 128+tm*4
// (16B lane stride -> conflict-free LDS.128). W is pre-transposed to [K][256]
// (row 255 zeroed) into __device__ scratch. Epilogue restages through smem in
// two 32-column halves so all global stores are warp-contiguous.
// ---------------------------------------------------------------------------

#define KT 16
#define NT 64

__device__ __align__(256) float g_Wt13[1024 * 256];
__device__ __align__(256) float g_Wt26[512 * 256];
__device__ __align__(256) float g_Wt52[256 * 256];

__global__ void prep_kernel(const float* __restrict__ W13,
                            const float* __restrict__ W26,
                            const float* __restrict__ W52) {
    int idx = blockIdx.x * blockDim.x + threadIdx.x;
    // Wt[k*256 + m] = (m < 255) ? W[m*K + k] : 0
    if (idx < 1024 * 256) {
        int m = idx & 255, k = idx >> 8;
        g_Wt13[idx] = (m < 255) ? W13[m * 1024 + k] : 0.f;
    }
    if (idx < 512 * 256) {
        int m = idx & 255, k = idx >> 8;
        g_Wt26[idx] = (m < 255) ? W26[m * 512 + k] : 0.f;
    }
    if (idx < 256 * 256) {
        int m = idx & 255, k = idx >> 8;
        g_Wt52[idx] = (m < 255) ? W52[m * 256 + k] : 0.f;
    }
}

__device__ __forceinline__ float sigmoidf_(float v) {
    return 1.f / (1.f + __expf(-v));
}

// d.lo += a.lo*b.lo ; d.hi += a.hi*b.hi   (one issue slot, exact fp32 fma)
__device__ __forceinline__ void fma2_(unsigned long long& d,
                                      unsigned long long a,
                                      unsigned long long b) {
    asm("fma.rn.f32x2 %0, %1, %2, %0;" : "+l"(d) : "l"(a), "l"(b));
}

__device__ __forceinline__ unsigned long long dup2_(float v) {
    unsigned long long r;
    asm("mov.b64 %0, {%1, %1};" : "=l"(r) : "f"(v));
    return r;
}

__device__ __forceinline__ float2 unpack2_(unsigned long long v) {
    float2 r;
    asm("mov.b64 {%0, %1}, %2;" : "=f"(r.x), "=f"(r.y) : "l"(v));
    return r;
}

__global__ __launch_bounds__(256, 2)
void head_kernel(const float* __restrict__ F,
                 int head,                       // 0:13  1:26  2:52
                 const float* __restrict__ bias,
                 float* __restrict__ out,
                 int K, int S, int HW, float invS,
                 float aw0, float ah0, float aw1, float ah1, float aw2, float ah2)
{
    // smem reused: phase 1 = W tile [16][256] f32 (4096 f) +
    //                        F tile [16][64] dup-pairs (1024 u64 = 2048 f)
    //              phase 2 = output stage [256][33] (8448 f)
    __shared__ __align__(16) float smem[8448];
    float* sW = smem;                                          // [KT][256]
    unsigned long long* sFd = (unsigned long long*)(smem + KT * 256); // [KT][NT]

    const float* __restrict__ Wt =
        (head == 0) ? g_Wt13 : (head == 1) ? g_Wt26 : g_Wt52;

    const int tid = threadIdx.x;
    const int tm  = tid & 31;      // lane: 32 threads along M
    const int tn  = tid >> 5;      // warp: 8 threads along N (8 cols each)
    const int n0  = blockIdx.x * NT;
    const int b   = blockIdx.y;

    const float* __restrict__ Fb = F + (size_t)b * K * HW;

    // acc2[i][j]: i selects M row-pair (i<2: rows tm*4+2i{,+1};
    //             i>=2: rows 128+tm*4+2(i-2){,+1}); j: column tn*8+j
    unsigned long long acc2[4][8];
#pragma unroll
    for (int i = 0; i < 4; i++)
#pragma unroll
        for (int j = 0; j < 8; j++) acc2[i][j] = 0ull;

    for (int k0 = 0; k0 < K; k0 += KT) {
        // W tile: 4096 contiguous floats (rows k0..k0+15 of Wt) -> float4 copy
        const float4* __restrict__ src = (const float4*)(Wt + (size_t)k0 * 256);
        float4* dstW = (float4*)sW;
#pragma unroll
        for (int r = 0; r < 4; r++) dstW[tid + 256 * r] = src[tid + 256 * r];
        // F tile: 16 x 64, coalesced along n, stored duplicated {v,v}
#pragma unroll
        for (int r = 0; r < 4; r++) {
            int e  = tid + 256 * r;
            int kk = e >> 6;
            int nn = e & 63;
            int gn = n0 + nn;
            float v = (gn < HW) ? Fb[(size_t)(k0 + kk) * HW + gn] : 0.f;
            sFd[kk * NT + nn] = dup2_(v);
        }
        __syncthreads();
#pragma unroll
        for (int kk = 0; kk < KT; kk++) {
            // a: two conflict-free LDS.128 -> 4 M-adjacent f32x2 pairs
            ulonglong2 a0 = *(const ulonglong2*)&sW[kk * 256 + tm * 4];
            ulonglong2 a1 = *(const ulonglong2*)&sW[kk * 256 + 128 + tm * 4];
            unsigned long long a2[4] = {a0.x, a0.y, a1.x, a1.y};
            // b: 8 duplicated pairs via 4 broadcast LDS.128
            const ulonglong2* bp = (const ulonglong2*)&sFd[kk * NT + tn * 8];
            ulonglong2 b0 = bp[0], b1 = bp[1], b2 = bp[2], b3 = bp[3];
            unsigned long long bd[8] = {b0.x, b0.y, b1.x, b1.y,
                                        b2.x, b2.y, b3.x, b3.y};
#pragma unroll
            for (int i = 0; i < 4; i++)
#pragma unroll
                for (int j = 0; j < 8; j++)
                    fma2_(acc2[i][j], a2[i], bd[j]);
        }
        __syncthreads();
    }

    // Epilogue in two 32-column halves (stage buffer is [256][33]).
    const int m    = tid;
    const int a_   = (m < 255) ? (m / 85) : 0;
    const int attr = m - a_ * 85;
    const float bm = (m < 255) ? bias[m] : 0.f;
    float aw, ah;
    if (a_ == 0)      { aw = aw0; ah = ah0; }
    else if (a_ == 1) { aw = aw1; ah = ah1; }
    else              { aw = aw2; ah = ah2; }
    float* __restrict__ outb =
        out + ((size_t)b * 3 * HW + (size_t)a_ * HW) * 85;

#pragma unroll
    for (int h = 0; h < 2; h++) {
        __syncthreads();
        // stage: warps tn in [4h, 4h+4) own columns [h*32, h*32+32)
        if ((tn >> 2) == h) {
            int cbase = (tn & 3) * 8;
#pragma unroll
            for (int i = 0; i < 4; i++) {
                int mrow = (i < 2) ? (tm * 4 + 2 * i) : (128 + tm * 4 + 2 * (i - 2));
#pragma unroll
                for (int j = 0; j < 8; j++) {
                    float2 v = unpack2_(acc2[i][j]);
                    smem[mrow * 33 + cbase + j]       = v.x;
                    smem[(mrow + 1) * 33 + cbase + j] = v.y;
                }
            }
        }
        __syncthreads();
        // thread tid = channel m; contiguous channels -> coalesced stores
        if (m < 255) {
#pragma unroll 4
            for (int nn = 0; nn < 32; nn++) {
                int gn = n0 + h * 32 + nn;
                if (gn >= HW) break;
                float v = smem[m * 33 + nn] + bm;
                float res;
                if (attr == 0) {
                    res = ((float)(gn % S) + sigmoidf_(v)) * invS;      // bx
                } else if (attr == 1) {
                    res = ((float)(gn / S) + sigmoidf_(v)) * invS;      // by
                } else if (attr == 2) {
                    res = __expf(v) * aw;                               // bw
                } else if (attr == 3) {
                    res = __expf(v) * ah;                               // bh
                } else {
                    res = sigmoidf_(v);                                 // conf / cls
                }
                outb[(size_t)gn * 85 + attr] = res;
            }
        }
    }
}

extern "C" void kernel_launch(void* const* d_in, const int* in_sizes, int n_in,
                              void* d_out, int out_size) {
    const float* f13 = (const float*)d_in[0];
    const float* f26 = (const float*)d_in[1];
    const float* f52 = (const float*)d_in[2];
    const float* W13 = (const float*)d_in[3];
    const float* b13 = (const float*)d_in[4];
    const float* W26 = (const float*)d_in[5];
    const float* b26 = (const float*)d_in[6];
    const float* W52 = (const float*)d_in[7];
    const float* b52 = (const float*)d_in[8];
    float* out = (float*)d_out;

    (void)in_sizes; (void)n_in; (void)out_size;

    const int B = 32;
    const size_t off26 = (size_t)B * 3 * 169 * 85;              // after out13
    const size_t off52 = off26 + (size_t)B * 3 * 676 * 85;      // after out26

    // Transpose / pad W matrices into device scratch.
    prep_kernel<<<1024, 256>>>(W13, W26, W52);

    const float inv416 = 1.f / 416.f;

    // head13: K=1024, S=13, HW=169, anchors (116,90)(156,198)(373,326)
    {
        dim3 grid((169 + NT - 1) / NT, B);
        head_kernel<<<grid, 256>>>(f13, 0, b13, out,
                                   1024, 13, 169, 1.f / 13.f,
                                   116.f * inv416, 90.f * inv416,
                                   156.f * inv416, 198.f * inv416,
                                   373.f * inv416, 326.f * inv416);
    }
    // head26: K=512, S=26, HW=676, anchors (30,61)(62,45)(59,119)
    {
        dim3 grid((676 + NT - 1) / NT, B);
        head_kernel<<<grid, 256>>>(f26, 1, b26, out + off26,
                                   512, 26, 676, 1.f / 26.f,
                                   30.f * inv416, 61.f * inv416,
                                   62.f * inv416, 45.f * inv416,
                                   59.f * inv416, 119.f * inv416);
    }
    // head52: K=256, S=52, HW=2704, anchors (10,13)(16,30)(33,23)
    {
        dim3 grid((2704 + NT - 1) / NT, B);
        head_kernel<<<grid, 256>>>(f52, 2, b52, out + off52,
                                   256, 52, 2704, 1.f / 52.f,
                                   10.f * inv416, 13.f * inv416,
                                   16.f * inv416, 30.f * inv416,
                                   33.f * inv416, 23.f * inv416);
    }
}